// round 4
// baseline (speedup 1.0000x reference)
#include <cuda_runtime.h>
#include <cuda_bf16.h>
#include <math_constants.h>

#define B 4
#define NPTS 1024
#define KNB 80

// ---------------- scratch (device globals; no allocation allowed) ----------------
__device__ float g_G[(size_t)B * NPTS * NPTS];          // neg_dist matrices
__device__ int   g_idx[B * NPTS * KNB];                 // knn indices
__device__ float g_u[(size_t)B * NPTS * 128];           // (b,n,o) W1·x
__device__ float g_v[(size_t)B * NPTS * 128];           // (b,n,o) (W2-W1)·x
__device__ float g_ymaxE[(size_t)B * NPTS * 128];       // per (b,n,o) max_k y
__device__ float g_yminE[(size_t)B * NPTS * 128];
__device__ double g_gs[48];                             // edge-layer group sums (16/layer)
__device__ unsigned int g_ymax[B * 1024];               // final head max/min (encoded)
__device__ unsigned int g_ymin[B * 1024];
__device__ double g_gs5[64];                            // final head group sums

// monotone float<->uint encoding for atomic max/min
__device__ __forceinline__ unsigned int fenc(float f) {
    unsigned int b = __float_as_uint(f);
    return (b & 0x80000000u) ? ~b : (b | 0x80000000u);
}
__device__ __forceinline__ float fdec(unsigned int u) {
    unsigned int b = (u & 0x80000000u) ? (u & 0x7FFFFFFFu) : ~u;
    return __uint_as_float(b);
}

// ---------------- one upfront zero kernel ----------------
__global__ void zero_all_kernel() {
    int i = blockIdx.x * 256 + threadIdx.x;
    if (i < B * 1024) { g_ymax[i] = 0u; g_ymin[i] = 0xFFFFFFFFu; }
    if (i < 48) g_gs[i] = 0.0;
    if (i < 64) g_gs5[i] = 0.0;
}

// ---------------- gram + fused xx: writes neg_dist = 2*x^T x - xx_n - xx_m ----------------
// 128x128 tile, 256 threads, 8x8 per thread
__global__ __launch_bounds__(256) void gram_kernel(const float* __restrict__ x, int bstride, int C) {
    int b = blockIdx.z;
    int n0 = blockIdx.y * 128, m0 = blockIdx.x * 128;
    __shared__ float As[32][132];
    __shared__ float Bs[32][132];
    int t = threadIdx.x;
    int tx = t & 15, ty = t >> 4;
    float acc[8][8] = {};
    float sa[8] = {}, sb[8] = {};
    const float* xb = x + (size_t)b * bstride;
    for (int cc = 0; cc < C; cc += 32) {
        int CH = min(32, C - cc);
        for (int i = t; i < 32 * 128; i += 256) {
            int c = i >> 7, l = i & 127;
            float av = 0.f, bv = 0.f;
            if (c < CH) {
                av = xb[(size_t)(cc + c) * NPTS + n0 + l];
                bv = xb[(size_t)(cc + c) * NPTS + m0 + l];
            }
            As[c][l] = av; Bs[c][l] = bv;
        }
        __syncthreads();
        for (int c = 0; c < CH; c++) {
            float a[8], bb[8];
            const float4* a4 = (const float4*)&As[c][ty * 8];
            const float4* b4 = (const float4*)&Bs[c][tx * 8];
            float4 av0 = a4[0], av1 = a4[1];
            float4 bv0 = b4[0], bv1 = b4[1];
            a[0]=av0.x;a[1]=av0.y;a[2]=av0.z;a[3]=av0.w;a[4]=av1.x;a[5]=av1.y;a[6]=av1.z;a[7]=av1.w;
            bb[0]=bv0.x;bb[1]=bv0.y;bb[2]=bv0.z;bb[3]=bv0.w;bb[4]=bv1.x;bb[5]=bv1.y;bb[6]=bv1.z;bb[7]=bv1.w;
#pragma unroll
            for (int i = 0; i < 8; i++) sa[i] = fmaf(a[i], a[i], sa[i]);
#pragma unroll
            for (int j = 0; j < 8; j++) sb[j] = fmaf(bb[j], bb[j], sb[j]);
#pragma unroll
            for (int i = 0; i < 8; i++)
#pragma unroll
                for (int j = 0; j < 8; j++) acc[i][j] = fmaf(a[i], bb[j], acc[i][j]);
        }
        __syncthreads();
    }
    float* Gb = g_G + ((size_t)b << 20);
#pragma unroll
    for (int i = 0; i < 8; i++) {
        float* row = Gb + (size_t)(n0 + ty * 8 + i) * NPTS + m0 + tx * 8;
#pragma unroll
        for (int j = 0; j < 8; j++)
            row[j] = 2.f * acc[i][j] - sa[i] - sb[j];
    }
}

// ---------------- knn: top-80 per row, 4-pass radix select, warp-aggregated ----------------
__global__ __launch_bounds__(256) void knn_kernel() {
    int bn = blockIdx.x;
    int b = bn >> 10;
    __shared__ unsigned int skeys[NPTS];
    __shared__ int hist[256];
    __shared__ int wtot[8];
    __shared__ int s_bsel, s_above, s_cnt, s_ecnt;
    __shared__ int s_eq[128];
    const float4* nd4 = (const float4*)(g_G + ((size_t)b << 20) + ((size_t)(bn & 1023) << 10));
    int t = threadIdx.x;
    int lane = t & 31, w = t >> 5;
    float4 d = nd4[t];
    unsigned int rkeys[4] = { fenc(d.x), fenc(d.y), fenc(d.z), fenc(d.w) };
    ((uint4*)skeys)[t] = make_uint4(rkeys[0], rkeys[1], rkeys[2], rkeys[3]);
    unsigned int prefix = 0, pmask = 0;
    int need = KNB;
    for (int shift = 24; shift >= 0; shift -= 8) {
        hist[t] = 0;
        __syncthreads();
#pragma unroll
        for (int j = 0; j < 4; j++) {
            unsigned int k = rkeys[j];
            bool act = ((k & pmask) == prefix);
            int bin = act ? (int)((k >> shift) & 255) : (300 + j);
            unsigned int m = __match_any_sync(0xffffffffu, bin);
            if (act && ((m & ((1u << lane) - 1u)) == 0u))
                atomicAdd(&hist[bin], __popc(m));
        }
        __syncthreads();
        int c = hist[t];
        int s = c;
#pragma unroll
        for (int off = 1; off < 32; off <<= 1) {
            int o = __shfl_down_sync(0xffffffffu, s, off);
            if (lane + off < 32) s += o;
        }
        if (lane == 0) wtot[w] = s;
        __syncthreads();
        int offsum = 0;
        for (int w2 = w + 1; w2 < 8; w2++) offsum += wtot[w2];
        int sfx = s + offsum;
        int nxt = sfx - c;
        if (sfx >= need && nxt < need) { s_bsel = t; s_above = nxt; }
        __syncthreads();
        prefix |= ((unsigned int)s_bsel) << shift;
        pmask  |= 255u << shift;
        need   -= s_above;
        __syncthreads();
    }
    if (t == 0) { s_cnt = 0; s_ecnt = 0; }
    __syncthreads();
    int* out = g_idx + bn * KNB;
#pragma unroll
    for (int j = 0; j < 4; j++) {
        unsigned int k = rkeys[j];
        int idx = 4 * t + j;
        bool gt = (k > prefix);
        unsigned int bal = __ballot_sync(0xffffffffu, gt);
        if (bal) {
            int ldr = __ffs(bal) - 1;
            int base = 0;
            if (lane == ldr) base = atomicAdd(&s_cnt, __popc(bal));
            base = __shfl_sync(0xffffffffu, base, ldr);
            if (gt) out[base + __popc(bal & ((1u << lane) - 1u))] = idx;
        }
        bool eq = (k == prefix);
        unsigned int be = __ballot_sync(0xffffffffu, eq);
        if (be) {
            int ldr = __ffs(be) - 1;
            int base = 0;
            if (lane == ldr) base = atomicAdd(&s_ecnt, __popc(be));
            base = __shfl_sync(0xffffffffu, base, ldr);
            if (eq) {
                int p = base + __popc(be & ((1u << lane) - 1u));
                if (p < 128) s_eq[p] = idx;
            }
        }
    }
    __syncthreads();
    if (t == 0) {
        int p = s_cnt;           // == KNB - need
        int L = s_ecnt;
        if (L == need && L <= 128) {
            for (int i = 0; i < L; i++) out[p++] = s_eq[i];
        } else if (L <= 128) {
            for (int r = 0; r < need; r++) {
                int bi = -1, bv = 0x7FFFFFFF;
                for (int i = 0; i < L; i++) {
                    int v = s_eq[i];
                    if (v >= 0 && v < bv) { bv = v; bi = i; }
                }
                out[p++] = bv;
                s_eq[bi] = -1;
            }
        } else {
            for (int i = 0; i < NPTS && p < KNB; i++)
                if (skeys[i] == prefix) out[p++] = i;
        }
    }
}

// ---------------- u/v projections: u=W1 x, v=(W2-W1) x, layout (b,n,o) ----------------
__global__ void uv_kernel(const float* __restrict__ x, int bstride,
                          const float* __restrict__ W, int Cin, int Cout) {
    int tid = blockIdx.x * blockDim.x + threadIdx.x;
    int total = B * NPTS * Cout;
    if (tid >= total) return;
    int o = tid % Cout;
    int n = (tid / Cout) & 1023;
    int b = tid / (Cout * NPTS);
    const float* xb = x + (size_t)b * bstride + n;
    const float* w = W + (size_t)o * 2 * Cin;
    float u = 0.f, v = 0.f;
    for (int c = 0; c < Cin; c++) {
        float xv = xb[(size_t)c * NPTS];
        float w1 = w[c], w2 = w[Cin + c];
        u = fmaf(w1, xv, u);
        v = fmaf(w2 - w1, xv, v);
    }
    g_u[tid] = u;
    g_v[tid] = v;
}

// ---------------- gather + max/min + group stats (float4, 4-wide MLP) ----------------
__global__ __launch_bounds__(256) void edge_agg_kernel(int Cout, int gsoff) {
    int TPP = Cout >> 2;          // threads per point (16 or 32)
    int ppb = 256 / TPP;          // points per block (16 or 8)
    int t = threadIdx.x;
    int p = t / TPP, o4 = t % TPP;
    int bn = blockIdx.x * ppb + p;
    int b = bn >> 10;
    __shared__ int sidx[16][KNB];
    __shared__ double sacc[4];
    if (t < 4) sacc[t] = 0.0;
    for (int i = t; i < ppb * KNB; i += 256)
        sidx[i / KNB][i % KNB] = g_idx[(blockIdx.x * ppb + i / KNB) * KNB + i % KNB];
    __syncthreads();
    int rs = Cout >> 2;
    const float4* ub = (const float4*)g_u + ((size_t)(b << 10)) * rs;
    float4 mx = make_float4(-CUDART_INF_F, -CUDART_INF_F, -CUDART_INF_F, -CUDART_INF_F);
    float4 mn = make_float4(CUDART_INF_F, CUDART_INF_F, CUDART_INF_F, CUDART_INF_F);
    float4 s1 = make_float4(0, 0, 0, 0), s2 = make_float4(0, 0, 0, 0);
    const int* myidx = sidx[p];
    for (int k = 0; k < KNB; k += 4) {
        int j0 = myidx[k], j1 = myidx[k + 1], j2 = myidx[k + 2], j3 = myidx[k + 3];
        float4 v0 = ub[(size_t)j0 * rs + o4];
        float4 v1 = ub[(size_t)j1 * rs + o4];
        float4 v2 = ub[(size_t)j2 * rs + o4];
        float4 v3 = ub[(size_t)j3 * rs + o4];
#define ACC(vv) \
        mx.x = fmaxf(mx.x, vv.x); mn.x = fminf(mn.x, vv.x); s1.x += vv.x; s2.x = fmaf(vv.x, vv.x, s2.x); \
        mx.y = fmaxf(mx.y, vv.y); mn.y = fminf(mn.y, vv.y); s1.y += vv.y; s2.y = fmaf(vv.y, vv.y, s2.y); \
        mx.z = fmaxf(mx.z, vv.z); mn.z = fminf(mn.z, vv.z); s1.z += vv.z; s2.z = fmaf(vv.z, vv.z, s2.z); \
        mx.w = fmaxf(mx.w, vv.w); mn.w = fminf(mn.w, vv.w); s1.w += vv.w; s2.w = fmaf(vv.w, vv.w, s2.w);
        ACC(v0) ACC(v1) ACC(v2) ACC(v3)
#undef ACC
    }
    float4 v = ((const float4*)g_v)[(size_t)bn * rs + o4];
    float4 ymx = make_float4(mx.x + v.x, mx.y + v.y, mx.z + v.z, mx.w + v.w);
    float4 ymn = make_float4(mn.x + v.x, mn.y + v.y, mn.z + v.z, mn.w + v.w);
    ((float4*)g_ymaxE)[(size_t)bn * rs + o4] = ymx;
    ((float4*)g_yminE)[(size_t)bn * rs + o4] = ymn;
    const float Kf = (float)KNB;
    float S1 = (s1.x + Kf * v.x) + (s1.y + Kf * v.y) + (s1.z + Kf * v.z) + (s1.w + Kf * v.w);
    float S2 = (s2.x + 2.f * v.x * s1.x + Kf * v.x * v.x)
             + (s2.y + 2.f * v.y * s1.y + Kf * v.y * v.y)
             + (s2.z + 2.f * v.z * s1.z + Kf * v.z * v.z)
             + (s2.w + 2.f * v.w * s1.w + Kf * v.w * v.w);
    int half = TPP >> 1;                // lanes per group segment
    int lane = t & 31;
#pragma unroll
    for (int off = 16; off > 0; off >>= 1) {
        if (off < half) {
            S1 += __shfl_down_sync(0xffffffffu, S1, off, half);
            S2 += __shfl_down_sync(0xffffffffu, S2, off, half);
        }
    }
    if ((lane & (half - 1)) == 0) {
        int g = (lane / half) & 1;
        atomicAdd(&sacc[g * 2 + 0], (double)S1);
        atomicAdd(&sacc[g * 2 + 1], (double)S2);
    }
    __syncthreads();
    if (t == 0) {
        atomicAdd(&g_gs[gsoff + (b * 2 + 0) * 2 + 0], sacc[0]);
        atomicAdd(&g_gs[gsoff + (b * 2 + 0) * 2 + 1], sacc[1]);
        atomicAdd(&g_gs[gsoff + (b * 2 + 1) * 2 + 0], sacc[2]);
        atomicAdd(&g_gs[gsoff + (b * 2 + 1) * 2 + 1], sacc[3]);
    }
}

// ---------------- GN + leaky + transpose-write layer output into x_features ----------------
// grid (N/32, Cout/32, B), block 256; 32x32 smem transpose tiles
__global__ __launch_bounds__(256) void edge_out_kernel(int Cout, int gsoff,
                                const float* __restrict__ gnw,
                                const float* __restrict__ gnb,
                                float* __restrict__ feat, int choff) {
    int b = blockIdx.z;
    int n0 = blockIdx.x * 32, o0 = blockIdx.y * 32;
    __shared__ float tmx[32][33], tmn[32][33];
    __shared__ float sA[32], sB[32];
    int t = threadIdx.x;
    int ol = t & 31, row8 = t >> 5;
    const float* mxb = g_ymaxE + ((size_t)(b << 10)) * Cout;
    const float* mnb = g_yminE + ((size_t)(b << 10)) * Cout;
#pragma unroll
    for (int p = 0; p < 4; p++) {
        int nl = row8 + p * 8;
        tmx[nl][ol] = mxb[(size_t)(n0 + nl) * Cout + o0 + ol];
        tmn[nl][ol] = mnb[(size_t)(n0 + nl) * Cout + o0 + ol];
    }
    if (t < 32) {
        int o = o0 + t;
        int g = o / (Cout >> 1);
        double cnt = (double)(Cout >> 1) * (double)NPTS * (double)KNB;
        double S1 = g_gs[gsoff + (b * 2 + g) * 2 + 0];
        double S2 = g_gs[gsoff + (b * 2 + g) * 2 + 1];
        double mud = S1 / cnt;
        float var = (float)(S2 / cnt - mud * mud);
        float rs = rsqrtf(var + 1e-5f);
        float a = gnw[o] * rs;
        sA[t] = a;
        sB[t] = gnb[o] - (float)mud * a;
    }
    __syncthreads();
#pragma unroll
    for (int p = 0; p < 4; p++) {
        int orow = row8 + p * 8;
        float a = sA[orow], bb = sB[orow];
        float c1 = fmaf(a, tmx[ol][orow], bb);
        float c2 = fmaf(a, tmn[ol][orow], bb);
        c1 = c1 >= 0.f ? c1 : 0.2f * c1;
        c2 = c2 >= 0.f ? c2 : 0.2f * c2;
        feat[(size_t)b * 262144 + (size_t)(choff + o0 + orow) * NPTS + n0 + ol] = fmaxf(c1, c2);
    }
}

// ---------------- final head matmul: 128x128 tile, 8x8/thread, fused stats ----------------
__global__ __launch_bounds__(256) void final_mm_kernel(const float* __restrict__ feat,
                                const float* __restrict__ W,
                                const float* __restrict__ bias) {
    int b = blockIdx.z;
    int co0 = blockIdx.x * 128;
    int n0 = blockIdx.y * 128;
    __shared__ float Ws[32][132];
    __shared__ float Xs[32][128];
    int t = threadIdx.x, tx = t & 15, ty = t >> 4;
    int lane = t & 31, w = t >> 5;
    float acc[8][8] = {};
    const float* fb = feat + (size_t)b * 262144;
    for (int cc = 0; cc < 256; cc += 32) {
        for (int i = t; i < 32 * 128; i += 256) {
            int row = i >> 5, c = i & 31;
            Ws[c][row] = W[(size_t)(co0 + row) * 256 + cc + c];
        }
        for (int i = t; i < 32 * 128; i += 256) {
            int nl = i & 127, c = i >> 7;
            Xs[c][nl] = fb[(size_t)(cc + c) * NPTS + n0 + nl];
        }
        __syncthreads();
#pragma unroll
        for (int c = 0; c < 32; c++) {
            float wv[8], xv[8];
            const float4* w4 = (const float4*)&Ws[c][ty * 8];
            const float4* x4 = (const float4*)&Xs[c][tx * 8];
            float4 a0 = w4[0], a1 = w4[1], b0 = x4[0], b1 = x4[1];
            wv[0]=a0.x;wv[1]=a0.y;wv[2]=a0.z;wv[3]=a0.w;wv[4]=a1.x;wv[5]=a1.y;wv[6]=a1.z;wv[7]=a1.w;
            xv[0]=b0.x;xv[1]=b0.y;xv[2]=b0.z;xv[3]=b0.w;xv[4]=b1.x;xv[5]=b1.y;xv[6]=b1.z;xv[7]=b1.w;
#pragma unroll
            for (int i = 0; i < 8; i++)
#pragma unroll
                for (int j = 0; j < 8; j++) acc[i][j] = fmaf(wv[i], xv[j], acc[i][j]);
        }
        __syncthreads();
    }
    float s1t = 0.f, s2t = 0.f;
#pragma unroll
    for (int i = 0; i < 8; i++) {
        int co = co0 + ty * 8 + i;
        float bv = bias[co];
        float mx = -CUDART_INF_F, mn = CUDART_INF_F;
#pragma unroll
        for (int j = 0; j < 8; j++) {
            float y = acc[i][j] + bv;
            mx = fmaxf(mx, y); mn = fminf(mn, y);
            s1t += y; s2t = fmaf(y, y, s2t);
        }
#pragma unroll
        for (int off = 8; off > 0; off >>= 1) {
            mx = fmaxf(mx, __shfl_down_sync(0xffffffffu, mx, off, 16));
            mn = fminf(mn, __shfl_down_sync(0xffffffffu, mn, off, 16));
        }
        if (tx == 0) {
            atomicMax(&g_ymax[b * 1024 + co], fenc(mx));
            atomicMin(&g_ymin[b * 1024 + co], fenc(mn));
        }
    }
#pragma unroll
    for (int off = 16; off > 0; off >>= 1) {
        s1t += __shfl_down_sync(0xffffffffu, s1t, off);
        s2t += __shfl_down_sync(0xffffffffu, s2t, off);
    }
    __shared__ double sred[8][2];
    if (lane == 0) { sred[w][0] = (double)s1t; sred[w][1] = (double)s2t; }
    __syncthreads();
    if (t == 0) {
        double a = 0.0, c = 0.0;
        for (int i = 0; i < 8; i++) { a += sred[i][0]; c += sred[i][1]; }
        int g = blockIdx.x;   // co-tile == group (128 channels)
        atomicAdd(&g_gs5[(b * 8 + g) * 2 + 0], a);
        atomicAdd(&g_gs5[(b * 8 + g) * 2 + 1], c);
    }
}

// ---------------- final head: GN + relu + max-over-N via endpoints ----------------
__global__ void final_out_kernel(const float* __restrict__ gnw,
                                 const float* __restrict__ gnb,
                                 float* __restrict__ out) {
    int i = blockIdx.x * 256 + threadIdx.x;
    if (i >= B * 1024) return;
    int b = i >> 10, c = i & 1023;
    int g = c >> 7;
    double cnt = 128.0 * 1024.0;
    double S1 = g_gs5[(b * 8 + g) * 2 + 0], S2 = g_gs5[(b * 8 + g) * 2 + 1];
    double mud = S1 / cnt;
    float var = (float)(S2 / cnt - mud * mud);
    float mu = (float)mud;
    float rs = rsqrtf(var + 1e-5f);
    float a = gnw[c] * rs;
    float bb = gnb[c] - mu * a;
    float ymx = fdec(g_ymax[i]), ymn = fdec(g_ymin[i]);
    float c1 = fmaxf(fmaf(a, ymx, bb), 0.f);
    float c2 = fmaxf(fmaf(a, ymn, bb), 0.f);
    out[i] = fmaxf(c1, c2);
}

// ---------------- launch ----------------
extern "C" void kernel_launch(void* const* d_in, const int* in_sizes, int n_in,
                              void* d_out, int out_size) {
    const float* x    = (const float*)d_in[0];
    const float* c1w  = (const float*)d_in[1];
    const float* g1w  = (const float*)d_in[2];
    const float* g1b  = (const float*)d_in[3];
    const float* c2w  = (const float*)d_in[4];
    const float* g2w  = (const float*)d_in[5];
    const float* g2b  = (const float*)d_in[6];
    const float* c3w  = (const float*)d_in[7];
    const float* g3w  = (const float*)d_in[8];
    const float* g3b  = (const float*)d_in[9];
    const float* mlpw = (const float*)d_in[10];
    const float* mlpb = (const float*)d_in[11];
    const float* g5w  = (const float*)d_in[12];
    const float* g5b  = (const float*)d_in[13];

    float* out  = (float*)d_out;
    float* feat = out + B * 1024;  // x_features region (B,256,N)

    struct L { const float* xin; int bstride, Cin, Cout, choff, gsoff;
               const float* W; const float* gw; const float* gb; };
    L layers[3] = {
        { x,                3 * NPTS,   3,   64, 0,   0,  c1w, g1w, g1b },
        { feat,             256 * NPTS, 64,  64, 64,  16, c2w, g2w, g2b },
        { feat + 64 * NPTS, 256 * NPTS, 64,  128, 128, 32, c3w, g3w, g3b },
    };

    zero_all_kernel<<<16, 256>>>();

    for (int li = 0; li < 3; li++) {
        L& l = layers[li];
        gram_kernel<<<dim3(8, 8, B), 256>>>(l.xin, l.bstride, l.Cin);
        knn_kernel<<<B * NPTS, 256>>>();
        int tot = B * NPTS * l.Cout;
        uv_kernel<<<tot / 256, 256>>>(l.xin, l.bstride, l.W, l.Cin, l.Cout);
        int ppb = 256 / (l.Cout >> 2);
        edge_agg_kernel<<<B * NPTS / ppb, 256>>>(l.Cout, l.gsoff);
        edge_out_kernel<<<dim3(32, l.Cout / 32, B), 256>>>(l.Cout, l.gsoff, l.gw, l.gb, feat, l.choff);
    }

    final_mm_kernel<<<dim3(8, 8, B), 256>>>(feat, mlpw, mlpb);
    final_out_kernel<<<16, 256>>>(g5w, g5b, out);
}

// round 5
// speedup vs baseline: 1.0037x; 1.0037x over previous
#include <cuda_runtime.h>
#include <cuda_bf16.h>
#include <math_constants.h>

#define B 4
#define NPTS 1024
#define KNB 80

// ---------------- scratch (device globals; no allocation allowed) ----------------
__device__ float g_G[(size_t)B * NPTS * NPTS];          // neg_dist matrices
__device__ int   g_idx[B * NPTS * KNB];                 // knn indices
__device__ float g_u[(size_t)B * NPTS * 128];           // (b,n,o) W1·x
__device__ float g_v[(size_t)B * NPTS * 128];           // (b,n,o) (W2-W1)·x
__device__ float g_ymaxE[(size_t)B * NPTS * 128];       // per (b,n,o) max_k y
__device__ float g_yminE[(size_t)B * NPTS * 128];
__device__ double g_gs[48];                             // edge-layer group sums (16/layer)
__device__ unsigned int g_ymax[B * 1024];               // final head max/min (encoded)
__device__ unsigned int g_ymin[B * 1024];
__device__ double g_gs5[64];                            // final head group sums

// monotone float<->uint encoding for atomic max/min
__device__ __forceinline__ unsigned int fenc(float f) {
    unsigned int b = __float_as_uint(f);
    return (b & 0x80000000u) ? ~b : (b | 0x80000000u);
}
__device__ __forceinline__ float fdec(unsigned int u) {
    unsigned int b = (u & 0x80000000u) ? (u & 0x7FFFFFFFu) : ~u;
    return __uint_as_float(b);
}

// ---------------- one upfront zero kernel ----------------
__global__ void zero_all_kernel() {
    int i = blockIdx.x * 256 + threadIdx.x;
    if (i < B * 1024) { g_ymax[i] = 0u; g_ymin[i] = 0xFFFFFFFFu; }
    if (i < 48) g_gs[i] = 0.0;
    if (i < 64) g_gs5[i] = 0.0;
}

// ---------------- gram + fused xx: writes neg_dist = 2*x^T x - xx_n - xx_m ----------------
// 128x128 tile, 256 threads, 8x8 per thread
__global__ __launch_bounds__(256) void gram_kernel(const float* __restrict__ x, int bstride, int C) {
    int b = blockIdx.z;
    int n0 = blockIdx.y * 128, m0 = blockIdx.x * 128;
    __shared__ float As[32][132];
    __shared__ float Bs[32][132];
    int t = threadIdx.x;
    int tx = t & 15, ty = t >> 4;
    float acc[8][8] = {};
    float sa[8] = {}, sb[8] = {};
    const float* xb = x + (size_t)b * bstride;
    for (int cc = 0; cc < C; cc += 32) {
        int CH = min(32, C - cc);
        for (int i = t; i < 32 * 128; i += 256) {
            int c = i >> 7, l = i & 127;
            float av = 0.f, bv = 0.f;
            if (c < CH) {
                av = xb[(size_t)(cc + c) * NPTS + n0 + l];
                bv = xb[(size_t)(cc + c) * NPTS + m0 + l];
            }
            As[c][l] = av; Bs[c][l] = bv;
        }
        __syncthreads();
        for (int c = 0; c < CH; c++) {
            float a[8], bb[8];
            const float4* a4 = (const float4*)&As[c][ty * 8];
            const float4* b4 = (const float4*)&Bs[c][tx * 8];
            float4 av0 = a4[0], av1 = a4[1];
            float4 bv0 = b4[0], bv1 = b4[1];
            a[0]=av0.x;a[1]=av0.y;a[2]=av0.z;a[3]=av0.w;a[4]=av1.x;a[5]=av1.y;a[6]=av1.z;a[7]=av1.w;
            bb[0]=bv0.x;bb[1]=bv0.y;bb[2]=bv0.z;bb[3]=bv0.w;bb[4]=bv1.x;bb[5]=bv1.y;bb[6]=bv1.z;bb[7]=bv1.w;
#pragma unroll
            for (int i = 0; i < 8; i++) sa[i] = fmaf(a[i], a[i], sa[i]);
#pragma unroll
            for (int j = 0; j < 8; j++) sb[j] = fmaf(bb[j], bb[j], sb[j]);
#pragma unroll
            for (int i = 0; i < 8; i++)
#pragma unroll
                for (int j = 0; j < 8; j++) acc[i][j] = fmaf(a[i], bb[j], acc[i][j]);
        }
        __syncthreads();
    }
    float* Gb = g_G + ((size_t)b << 20);
#pragma unroll
    for (int i = 0; i < 8; i++) {
        float* row = Gb + (size_t)(n0 + ty * 8 + i) * NPTS + m0 + tx * 8;
#pragma unroll
        for (int j = 0; j < 8; j++)
            row[j] = 2.f * acc[i][j] - sa[i] - sb[j];
    }
}

// ---------------- knn: top-80 per row, 4-pass radix select, warp-aggregated ----------------
__global__ __launch_bounds__(256) void knn_kernel() {
    int bn = blockIdx.x;
    int b = bn >> 10;
    __shared__ unsigned int skeys[NPTS];
    __shared__ int hist[256];
    __shared__ int wtot[8];
    __shared__ int s_bsel, s_above, s_cnt, s_ecnt;
    __shared__ int s_eq[128];
    const float4* nd4 = (const float4*)(g_G + ((size_t)b << 20) + ((size_t)(bn & 1023) << 10));
    int t = threadIdx.x;
    int lane = t & 31, w = t >> 5;
    float4 d = nd4[t];
    unsigned int rkeys[4] = { fenc(d.x), fenc(d.y), fenc(d.z), fenc(d.w) };
    ((uint4*)skeys)[t] = make_uint4(rkeys[0], rkeys[1], rkeys[2], rkeys[3]);
    unsigned int prefix = 0, pmask = 0;
    int need = KNB;
    for (int shift = 24; shift >= 0; shift -= 8) {
        hist[t] = 0;
        __syncthreads();
#pragma unroll
        for (int j = 0; j < 4; j++) {
            unsigned int k = rkeys[j];
            bool act = ((k & pmask) == prefix);
            int bin = act ? (int)((k >> shift) & 255) : (300 + j);
            unsigned int m = __match_any_sync(0xffffffffu, bin);
            if (act && ((m & ((1u << lane) - 1u)) == 0u))
                atomicAdd(&hist[bin], __popc(m));
        }
        __syncthreads();
        int c = hist[t];
        int s = c;
#pragma unroll
        for (int off = 1; off < 32; off <<= 1) {
            int o = __shfl_down_sync(0xffffffffu, s, off);
            if (lane + off < 32) s += o;
        }
        if (lane == 0) wtot[w] = s;
        __syncthreads();
        int offsum = 0;
        for (int w2 = w + 1; w2 < 8; w2++) offsum += wtot[w2];
        int sfx = s + offsum;
        int nxt = sfx - c;
        if (sfx >= need && nxt < need) { s_bsel = t; s_above = nxt; }
        __syncthreads();
        prefix |= ((unsigned int)s_bsel) << shift;
        pmask  |= 255u << shift;
        need   -= s_above;
        __syncthreads();
    }
    if (t == 0) { s_cnt = 0; s_ecnt = 0; }
    __syncthreads();
    int* out = g_idx + bn * KNB;
#pragma unroll
    for (int j = 0; j < 4; j++) {
        unsigned int k = rkeys[j];
        int idx = 4 * t + j;
        bool gt = (k > prefix);
        unsigned int bal = __ballot_sync(0xffffffffu, gt);
        if (bal) {
            int ldr = __ffs(bal) - 1;
            int base = 0;
            if (lane == ldr) base = atomicAdd(&s_cnt, __popc(bal));
            base = __shfl_sync(0xffffffffu, base, ldr);
            if (gt) out[base + __popc(bal & ((1u << lane) - 1u))] = idx;
        }
        bool eq = (k == prefix);
        unsigned int be = __ballot_sync(0xffffffffu, eq);
        if (be) {
            int ldr = __ffs(be) - 1;
            int base = 0;
            if (lane == ldr) base = atomicAdd(&s_ecnt, __popc(be));
            base = __shfl_sync(0xffffffffu, base, ldr);
            if (eq) {
                int p = base + __popc(be & ((1u << lane) - 1u));
                if (p < 128) s_eq[p] = idx;
            }
        }
    }
    __syncthreads();
    if (t == 0) {
        int p = s_cnt;           // == KNB - need
        int L = s_ecnt;
        if (L == need && L <= 128) {
            for (int i = 0; i < L; i++) out[p++] = s_eq[i];
        } else if (L <= 128) {
            for (int r = 0; r < need; r++) {
                int bi = -1, bv = 0x7FFFFFFF;
                for (int i = 0; i < L; i++) {
                    int v = s_eq[i];
                    if (v >= 0 && v < bv) { bv = v; bi = i; }
                }
                out[p++] = bv;
                s_eq[bi] = -1;
            }
        } else {
            for (int i = 0; i < NPTS && p < KNB; i++)
                if (skeys[i] == prefix) out[p++] = i;
        }
    }
}

// ---------------- u/v projections: u=W1 x, v=(W2-W1) x, layout (b,n,o) ----------------
__global__ void uv_kernel(const float* __restrict__ x, int bstride,
                          const float* __restrict__ W, int Cin, int Cout) {
    int tid = blockIdx.x * blockDim.x + threadIdx.x;
    int total = B * NPTS * Cout;
    if (tid >= total) return;
    int o = tid % Cout;
    int n = (tid / Cout) & 1023;
    int b = tid / (Cout * NPTS);
    const float* xb = x + (size_t)b * bstride + n;
    const float* w = W + (size_t)o * 2 * Cin;
    float u = 0.f, v = 0.f;
    for (int c = 0; c < Cin; c++) {
        float xv = xb[(size_t)c * NPTS];
        float w1 = w[c], w2 = w[Cin + c];
        u = fmaf(w1, xv, u);
        v = fmaf(w2 - w1, xv, v);
    }
    g_u[tid] = u;
    g_v[tid] = v;
}

// ---------------- gather + max/min + group stats (float4, 4-wide MLP) ----------------
__global__ __launch_bounds__(256) void edge_agg_kernel(int Cout, int gsoff) {
    int TPP = Cout >> 2;          // threads per point (16 or 32)
    int ppb = 256 / TPP;          // points per block (16 or 8)
    int t = threadIdx.x;
    int p = t / TPP, o4 = t % TPP;
    int bn = blockIdx.x * ppb + p;
    int b = bn >> 10;
    __shared__ int sidx[16][KNB];
    __shared__ double sacc[4];
    if (t < 4) sacc[t] = 0.0;
    for (int i = t; i < ppb * KNB; i += 256)
        sidx[i / KNB][i % KNB] = g_idx[(blockIdx.x * ppb + i / KNB) * KNB + i % KNB];
    __syncthreads();
    int rs = Cout >> 2;
    const float4* ub = (const float4*)g_u + ((size_t)(b << 10)) * rs;
    float4 mx = make_float4(-CUDART_INF_F, -CUDART_INF_F, -CUDART_INF_F, -CUDART_INF_F);
    float4 mn = make_float4(CUDART_INF_F, CUDART_INF_F, CUDART_INF_F, CUDART_INF_F);
    float4 s1 = make_float4(0, 0, 0, 0), s2 = make_float4(0, 0, 0, 0);
    const int* myidx = sidx[p];
    for (int k = 0; k < KNB; k += 4) {
        int j0 = myidx[k], j1 = myidx[k + 1], j2 = myidx[k + 2], j3 = myidx[k + 3];
        float4 v0 = ub[(size_t)j0 * rs + o4];
        float4 v1 = ub[(size_t)j1 * rs + o4];
        float4 v2 = ub[(size_t)j2 * rs + o4];
        float4 v3 = ub[(size_t)j3 * rs + o4];
#define ACC(vv) \
        mx.x = fmaxf(mx.x, vv.x); mn.x = fminf(mn.x, vv.x); s1.x += vv.x; s2.x = fmaf(vv.x, vv.x, s2.x); \
        mx.y = fmaxf(mx.y, vv.y); mn.y = fminf(mn.y, vv.y); s1.y += vv.y; s2.y = fmaf(vv.y, vv.y, s2.y); \
        mx.z = fmaxf(mx.z, vv.z); mn.z = fminf(mn.z, vv.z); s1.z += vv.z; s2.z = fmaf(vv.z, vv.z, s2.z); \
        mx.w = fmaxf(mx.w, vv.w); mn.w = fminf(mn.w, vv.w); s1.w += vv.w; s2.w = fmaf(vv.w, vv.w, s2.w);
        ACC(v0) ACC(v1) ACC(v2) ACC(v3)
#undef ACC
    }
    float4 v = ((const float4*)g_v)[(size_t)bn * rs + o4];
    float4 ymx = make_float4(mx.x + v.x, mx.y + v.y, mx.z + v.z, mx.w + v.w);
    float4 ymn = make_float4(mn.x + v.x, mn.y + v.y, mn.z + v.z, mn.w + v.w);
    ((float4*)g_ymaxE)[(size_t)bn * rs + o4] = ymx;
    ((float4*)g_yminE)[(size_t)bn * rs + o4] = ymn;
    const float Kf = (float)KNB;
    float S1 = (s1.x + Kf * v.x) + (s1.y + Kf * v.y) + (s1.z + Kf * v.z) + (s1.w + Kf * v.w);
    float S2 = (s2.x + 2.f * v.x * s1.x + Kf * v.x * v.x)
             + (s2.y + 2.f * v.y * s1.y + Kf * v.y * v.y)
             + (s2.z + 2.f * v.z * s1.z + Kf * v.z * v.z)
             + (s2.w + 2.f * v.w * s1.w + Kf * v.w * v.w);
    int half = TPP >> 1;                // lanes per group segment
    int lane = t & 31;
#pragma unroll
    for (int off = 16; off > 0; off >>= 1) {
        if (off < half) {
            S1 += __shfl_down_sync(0xffffffffu, S1, off, half);
            S2 += __shfl_down_sync(0xffffffffu, S2, off, half);
        }
    }
    if ((lane & (half - 1)) == 0) {
        int g = (lane / half) & 1;
        atomicAdd(&sacc[g * 2 + 0], (double)S1);
        atomicAdd(&sacc[g * 2 + 1], (double)S2);
    }
    __syncthreads();
    if (t == 0) {
        atomicAdd(&g_gs[gsoff + (b * 2 + 0) * 2 + 0], sacc[0]);
        atomicAdd(&g_gs[gsoff + (b * 2 + 0) * 2 + 1], sacc[1]);
        atomicAdd(&g_gs[gsoff + (b * 2 + 1) * 2 + 0], sacc[2]);
        atomicAdd(&g_gs[gsoff + (b * 2 + 1) * 2 + 1], sacc[3]);
    }
}

// ---------------- GN + leaky + transpose-write layer output into x_features ----------------
// grid (N/32, Cout/32, B), block 256; 32x32 smem transpose tiles
__global__ __launch_bounds__(256) void edge_out_kernel(int Cout, int gsoff,
                                const float* __restrict__ gnw,
                                const float* __restrict__ gnb,
                                float* __restrict__ feat, int choff) {
    int b = blockIdx.z;
    int n0 = blockIdx.x * 32, o0 = blockIdx.y * 32;
    __shared__ float tmx[32][33], tmn[32][33];
    __shared__ float sA[32], sB[32];
    int t = threadIdx.x;
    int ol = t & 31, row8 = t >> 5;
    const float* mxb = g_ymaxE + ((size_t)(b << 10)) * Cout;
    const float* mnb = g_yminE + ((size_t)(b << 10)) * Cout;
#pragma unroll
    for (int p = 0; p < 4; p++) {
        int nl = row8 + p * 8;
        tmx[nl][ol] = mxb[(size_t)(n0 + nl) * Cout + o0 + ol];
        tmn[nl][ol] = mnb[(size_t)(n0 + nl) * Cout + o0 + ol];
    }
    if (t < 32) {
        int o = o0 + t;
        int g = o / (Cout >> 1);
        double cnt = (double)(Cout >> 1) * (double)NPTS * (double)KNB;
        double S1 = g_gs[gsoff + (b * 2 + g) * 2 + 0];
        double S2 = g_gs[gsoff + (b * 2 + g) * 2 + 1];
        double mud = S1 / cnt;
        float var = (float)(S2 / cnt - mud * mud);
        float rs = rsqrtf(var + 1e-5f);
        float a = gnw[o] * rs;
        sA[t] = a;
        sB[t] = gnb[o] - (float)mud * a;
    }
    __syncthreads();
#pragma unroll
    for (int p = 0; p < 4; p++) {
        int orow = row8 + p * 8;
        float a = sA[orow], bb = sB[orow];
        float c1 = fmaf(a, tmx[ol][orow], bb);
        float c2 = fmaf(a, tmn[ol][orow], bb);
        c1 = c1 >= 0.f ? c1 : 0.2f * c1;
        c2 = c2 >= 0.f ? c2 : 0.2f * c2;
        feat[(size_t)b * 262144 + (size_t)(choff + o0 + orow) * NPTS + n0 + ol] = fmaxf(c1, c2);
    }
}

// ---------------- final head matmul: 128x128 tile, 8x8/thread, fused stats ----------------
__global__ __launch_bounds__(256) void final_mm_kernel(const float* __restrict__ feat,
                                const float* __restrict__ W,
                                const float* __restrict__ bias) {
    int b = blockIdx.z;
    int co0 = blockIdx.x * 128;
    int n0 = blockIdx.y * 128;
    __shared__ float Ws[32][132];
    __shared__ float Xs[32][128];
    int t = threadIdx.x, tx = t & 15, ty = t >> 4;
    int lane = t & 31, w = t >> 5;
    float acc[8][8] = {};
    const float* fb = feat + (size_t)b * 262144;
    for (int cc = 0; cc < 256; cc += 32) {
        for (int i = t; i < 32 * 128; i += 256) {
            int row = i >> 5, c = i & 31;
            Ws[c][row] = W[(size_t)(co0 + row) * 256 + cc + c];
        }
        for (int i = t; i < 32 * 128; i += 256) {
            int nl = i & 127, c = i >> 7;
            Xs[c][nl] = fb[(size_t)(cc + c) * NPTS + n0 + nl];
        }
        __syncthreads();
#pragma unroll
        for (int c = 0; c < 32; c++) {
            float wv[8], xv[8];
            const float4* w4 = (const float4*)&Ws[c][ty * 8];
            const float4* x4 = (const float4*)&Xs[c][tx * 8];
            float4 a0 = w4[0], a1 = w4[1], b0 = x4[0], b1 = x4[1];
            wv[0]=a0.x;wv[1]=a0.y;wv[2]=a0.z;wv[3]=a0.w;wv[4]=a1.x;wv[5]=a1.y;wv[6]=a1.z;wv[7]=a1.w;
            xv[0]=b0.x;xv[1]=b0.y;xv[2]=b0.z;xv[3]=b0.w;xv[4]=b1.x;xv[5]=b1.y;xv[6]=b1.z;xv[7]=b1.w;
#pragma unroll
            for (int i = 0; i < 8; i++)
#pragma unroll
                for (int j = 0; j < 8; j++) acc[i][j] = fmaf(wv[i], xv[j], acc[i][j]);
        }
        __syncthreads();
    }
    float s1t = 0.f, s2t = 0.f;
#pragma unroll
    for (int i = 0; i < 8; i++) {
        int co = co0 + ty * 8 + i;
        float bv = bias[co];
        float mx = -CUDART_INF_F, mn = CUDART_INF_F;
#pragma unroll
        for (int j = 0; j < 8; j++) {
            float y = acc[i][j] + bv;
            mx = fmaxf(mx, y); mn = fminf(mn, y);
            s1t += y; s2t = fmaf(y, y, s2t);
        }
#pragma unroll
        for (int off = 8; off > 0; off >>= 1) {
            mx = fmaxf(mx, __shfl_down_sync(0xffffffffu, mx, off, 16));
            mn = fminf(mn, __shfl_down_sync(0xffffffffu, mn, off, 16));
        }
        if (tx == 0) {
            atomicMax(&g_ymax[b * 1024 + co], fenc(mx));
            atomicMin(&g_ymin[b * 1024 + co], fenc(mn));
        }
    }
#pragma unroll
    for (int off = 16; off > 0; off >>= 1) {
        s1t += __shfl_down_sync(0xffffffffu, s1t, off);
        s2t += __shfl_down_sync(0xffffffffu, s2t, off);
    }
    __shared__ double sred[8][2];
    if (lane == 0) { sred[w][0] = (double)s1t; sred[w][1] = (double)s2t; }
    __syncthreads();
    if (t == 0) {
        double a = 0.0, c = 0.0;
        for (int i = 0; i < 8; i++) { a += sred[i][0]; c += sred[i][1]; }
        int g = blockIdx.x;   // co-tile == group (128 channels)
        atomicAdd(&g_gs5[(b * 8 + g) * 2 + 0], a);
        atomicAdd(&g_gs5[(b * 8 + g) * 2 + 1], c);
    }
}

// ---------------- final head: GN + relu + max-over-N via endpoints ----------------
__global__ void final_out_kernel(const float* __restrict__ gnw,
                                 const float* __restrict__ gnb,
                                 float* __restrict__ out) {
    int i = blockIdx.x * 256 + threadIdx.x;
    if (i >= B * 1024) return;
    int b = i >> 10, c = i & 1023;
    int g = c >> 7;
    double cnt = 128.0 * 1024.0;
    double S1 = g_gs5[(b * 8 + g) * 2 + 0], S2 = g_gs5[(b * 8 + g) * 2 + 1];
    double mud = S1 / cnt;
    float var = (float)(S2 / cnt - mud * mud);
    float mu = (float)mud;
    float rs = rsqrtf(var + 1e-5f);
    float a = gnw[c] * rs;
    float bb = gnb[c] - mu * a;
    float ymx = fdec(g_ymax[i]), ymn = fdec(g_ymin[i]);
    float c1 = fmaxf(fmaf(a, ymx, bb), 0.f);
    float c2 = fmaxf(fmaf(a, ymn, bb), 0.f);
    out[i] = fmaxf(c1, c2);
}

// ---------------- launch ----------------
extern "C" void kernel_launch(void* const* d_in, const int* in_sizes, int n_in,
                              void* d_out, int out_size) {
    const float* x    = (const float*)d_in[0];
    const float* c1w  = (const float*)d_in[1];
    const float* g1w  = (const float*)d_in[2];
    const float* g1b  = (const float*)d_in[3];
    const float* c2w  = (const float*)d_in[4];
    const float* g2w  = (const float*)d_in[5];
    const float* g2b  = (const float*)d_in[6];
    const float* c3w  = (const float*)d_in[7];
    const float* g3w  = (const float*)d_in[8];
    const float* g3b  = (const float*)d_in[9];
    const float* mlpw = (const float*)d_in[10];
    const float* mlpb = (const float*)d_in[11];
    const float* g5w  = (const float*)d_in[12];
    const float* g5b  = (const float*)d_in[13];

    float* out  = (float*)d_out;
    float* feat = out + B * 1024;  // x_features region (B,256,N)

    struct L { const float* xin; int bstride, Cin, Cout, choff, gsoff;
               const float* W; const float* gw; const float* gb; };
    L layers[3] = {
        { x,                3 * NPTS,   3,   64, 0,   0,  c1w, g1w, g1b },
        { feat,             256 * NPTS, 64,  64, 64,  16, c2w, g2w, g2b },
        { feat + 64 * NPTS, 256 * NPTS, 64,  128, 128, 32, c3w, g3w, g3b },
    };

    zero_all_kernel<<<16, 256>>>();

    for (int li = 0; li < 3; li++) {
        L& l = layers[li];
        gram_kernel<<<dim3(8, 8, B), 256>>>(l.xin, l.bstride, l.Cin);
        knn_kernel<<<B * NPTS, 256>>>();
        int tot = B * NPTS * l.Cout;
        uv_kernel<<<tot / 256, 256>>>(l.xin, l.bstride, l.W, l.Cin, l.Cout);
        int ppb = 256 / (l.Cout >> 2);
        edge_agg_kernel<<<B * NPTS / ppb, 256>>>(l.Cout, l.gsoff);
        edge_out_kernel<<<dim3(32, l.Cout / 32, B), 256>>>(l.Cout, l.gsoff, l.gw, l.gb, feat, l.choff);
    }

    final_mm_kernel<<<dim3(8, 8, B), 256>>>(feat, mlpw, mlpb);
    final_out_kernel<<<16, 256>>>(g5w, g5b, out);
}